// round 9
// baseline (speedup 1.0000x reference)
#include <cuda_runtime.h>
#include <math.h>

// x [L=4096, B=4, D=1024] fp32, channel-contiguous (BD = 4096 per timestep)
#define L    4096
#define B    4
#define D    1024
#define BD   (B * D)       // 4096 channels
#define C    32            // time chunks
#define LC   (L / C)       // 32 steps per chunk
#define GRID ((C * BD) / 256)   // 512 CTAs, all co-resident

// Per-channel coefficients
__device__ float g_cr[D], g_ci[D];   // c
__device__ float g_Ar[D], g_Ai[D];   // A = c^LC
// Chunk aggregates (zero-init local scan exit states), 1 MB — L2-resident
__device__ float g_er[C * BD], g_ei[C * BD];
// Grid barrier state (reset by k0 every launch -> graph-replay safe)
__device__ unsigned g_bar;
__device__ unsigned g_rel;

__device__ __forceinline__ unsigned ld_acquire(const unsigned* p) {
    unsigned v;
    asm volatile("ld.global.acquire.gpu.b32 %0, [%1];" : "=r"(v) : "l"(p));
    return v;
}
__device__ __forceinline__ void st_release(unsigned* p, unsigned v) {
    asm volatile("st.global.release.gpu.b32 [%0], %1;" :: "l"(p), "r"(v));
}

// ---------------------------------------------------------------------------
// K0: coefficients (double precision) + barrier reset.
// ---------------------------------------------------------------------------
__global__ void k0_setup(const float* __restrict__ lmlg,
                         const float* __restrict__ theta) {
    int d = blockIdx.x * blockDim.x + threadIdx.x;
    if (d == 0) { g_bar = 0; g_rel = 0; }
    if (d >= D) return;
    double g  = exp(-exp((double)lmlg[d]));
    double th = (double)theta[d];
    double cr = g * cos(th);
    double ci = g * sin(th);
    g_cr[d] = (float)cr;
    g_ci[d] = (float)ci;
    double ar = cr, ai = ci;            // A = c^128 via 7 squarings
#pragma unroll
    for (int i = 0; i < 7; i++) {
        double nr = ar * ar - ai * ai;
        double ni = 2.0 * ar * ai;
        ar = nr; ai = ni;
    }
    g_Ar[d] = (float)ar;
    g_Ai[d] = (float)ai;
}

// ---------------------------------------------------------------------------
// Fused kernel: local scan -> grid barrier -> per-thread prefix -> replay.
// x is loaded once into registers and reused after the barrier.
// ---------------------------------------------------------------------------
__global__ void __launch_bounds__(256, 4)
spiral_fused(const float* __restrict__ x,
             const float* __restrict__ lci,
             float* __restrict__ out) {
    int chunk = blockIdx.x >> 4;                   // 16 CTAs per chunk
    int bd    = ((blockIdx.x & 15) << 8) | threadIdx.x;
    int d     = bd & (D - 1);
    int tid   = chunk * BD + bd;

    float cr = g_cr[d], ci = g_ci[d];

    // ---- load full tile into registers (32 independent coalesced loads) ----
    float xv[LC];
    const float* xp = x + (size_t)chunk * LC * BD + bd;
#pragma unroll
    for (int k = 0; k < LC; k++)
        xv[k] = __ldg(xp + (size_t)k * BD);

    // ---- local zero-init scan -> aggregate E ----
    float sr = 0.f, si = 0.f;
#pragma unroll
    for (int k = 0; k < LC; k++) {
        float nr = fmaf(cr, sr, fmaf(-ci, si, xv[k]));
        float ni = fmaf(ci, sr, cr * si);
        sr = nr; si = ni;
    }
    g_er[tid] = sr;
    g_ei[tid] = si;

    // ---- grid-wide barrier (all 512 CTAs co-resident by launch_bounds) ----
    __threadfence();
    __syncthreads();
    if (threadIdx.x == 0) {
        unsigned n = atomicAdd(&g_bar, 1u);
        if (n == (unsigned)(gridDim.x - 1)) st_release(&g_rel, 1u);
        while (ld_acquire(&g_rel) == 0u) __nanosleep(20);
    }
    __syncthreads();

    // ---- per-thread prefix: P = sum_j A^{chunk-1-j} E_j + A^chunk * seed ----
    float Ar = g_Ar[d], Ai = g_Ai[d];
    float accR = 0.f, accI = 0.f;    // running sum
    float pwR = 1.f, pwI = 0.f;      // A^(chunk-1-j)
    for (int j = chunk - 1; j >= 0; j--) {
        float eR = g_er[j * BD + bd];
        float eI = g_ei[j * BD + bd];
        accR = fmaf(pwR, eR, fmaf(-pwI, eI, accR));
        accI = fmaf(pwR, eI, fmaf(pwI, eR, accI));
        float t = pwR * Ar - pwI * Ai;
        pwI = fmaf(pwR, Ai, pwI * Ar);
        pwR = t;
    }
    float seed = lci[d];
    float pr = fmaf(pwR, seed, accR);   // pw = A^chunk after the loop
    float pi = fmaf(pwI, seed, accI);

    // ---- replay from registers, out = Re(s) * x ----
    sr = pr; si = pi;
    float* op = out + (size_t)chunk * LC * BD + bd;
#pragma unroll
    for (int k = 0; k < LC; k++) {
        float nr = fmaf(cr, sr, fmaf(-ci, si, xv[k]));
        float ni = fmaf(ci, sr, cr * si);
        sr = nr; si = ni;
        __stcs(op + (size_t)k * BD, nr * xv[k]);
    }
}

// ---------------------------------------------------------------------------
extern "C" void kernel_launch(void* const* d_in, const int* in_sizes, int n_in,
                              void* d_out, int out_size) {
    const float* x    = (const float*)d_in[0];  // [L,B,D]
    const float* lmlg = (const float*)d_in[1];  // [D]
    const float* th   = (const float*)d_in[2];  // [D]
    const float* lci  = (const float*)d_in[3];  // [D]
    float* out = (float*)d_out;

    k0_setup<<<(D + 255) / 256, 256>>>(lmlg, th);
    spiral_fused<<<GRID, 256>>>(x, lci, out);
}

// round 10
// speedup vs baseline: 1.8711x; 1.8711x over previous
#include <cuda_runtime.h>
#include <math.h>

// x [L=4096, B=4, D=1024] fp32, channel-contiguous (BD = 4096 per timestep)
#define L    4096
#define B    4
#define D    1024
#define BD   (B * D)        // 4096 channels
#define C    32             // time chunks
#define LC   (L / C)        // 128 steps per chunk
#define UNR  16             // load batch (double-buffered)
#define GRID ((C * BD) / 256)   // 512 CTAs, all co-resident (<= 148*4)

// Spine: per-(chunk,channel) aggregates of the zero-init local scans (1 MB)
__device__ float g_er[C * BD], g_ei[C * BD];
// Self-resetting grid barrier state (zeroed by last CTA each launch)
__device__ unsigned g_bar, g_rel, g_done;

__device__ __forceinline__ unsigned ld_acquire(const unsigned* p) {
    unsigned v;
    asm volatile("ld.global.acquire.gpu.b32 %0, [%1];" : "=r"(v) : "l"(p));
    return v;
}
__device__ __forceinline__ void st_release(unsigned* p, unsigned v) {
    asm volatile("st.global.release.gpu.b32 [%0], %1;" :: "l"(p), "r"(v));
}

// ---------------------------------------------------------------------------
// Single fused kernel:
//   inline fp32 coefficients -> pipelined local scan (phase 1, x from DRAM)
//   -> grid barrier -> per-thread prefix from L2 spine
//   -> pipelined replay (phase 2, x from L2) + streaming stores.
// ---------------------------------------------------------------------------
__global__ void __launch_bounds__(256, 4)
spiral_fused(const float* __restrict__ x,
             const float* __restrict__ lmlg,
             const float* __restrict__ theta,
             const float* __restrict__ lci,
             float* __restrict__ out) {
    int chunk = blockIdx.x >> 4;                    // 16 CTAs per chunk
    int bd    = ((blockIdx.x & 15) << 8) | threadIdx.x;
    int d     = bd & (D - 1);
    int sidx  = chunk * BD + bd;

    // ---- coefficients, fp32 (error budget 1e-3; this costs ~1e-6) ----
    float gamma = __expf(-__expf(lmlg[d]));
    float snt, cst;
    __sincosf(theta[d], &snt, &cst);
    float cr = gamma * cst, ci = gamma * snt;
    float Ar = cr, Ai = ci;                         // A = c^128, 7 squarings
#pragma unroll
    for (int i = 0; i < 7; i++) {
        float t = Ar * Ar - Ai * Ai;
        Ai = 2.f * Ar * Ai;
        Ar = t;
    }

    // ---- phase 1: pipelined zero-init local scan (x read once from DRAM) ----
    const float* xp = x + (size_t)chunk * LC * BD + bd;
    float sr = 0.f, si = 0.f;
    {
        float xa[UNR], xb[UNR];
#pragma unroll
        for (int k = 0; k < UNR; k++)
            xa[k] = __ldg(xp + (size_t)k * BD);
        for (int n = UNR; n < LC; n += UNR) {
#pragma unroll
            for (int k = 0; k < UNR; k++)
                xb[k] = __ldg(xp + (size_t)(n + k) * BD);
#pragma unroll
            for (int k = 0; k < UNR; k++) {
                float nr = fmaf(cr, sr, fmaf(-ci, si, xa[k]));
                float ni = fmaf(ci, sr, cr * si);
                sr = nr; si = ni;
            }
#pragma unroll
            for (int k = 0; k < UNR; k++) xa[k] = xb[k];
        }
#pragma unroll
        for (int k = 0; k < UNR; k++) {
            float nr = fmaf(cr, sr, fmaf(-ci, si, xa[k]));
            float ni = fmaf(ci, sr, cr * si);
            sr = nr; si = ni;
        }
    }
    g_er[sidx] = sr;
    g_ei[sidx] = si;

    // ---- grid barrier (512 CTAs co-resident via __launch_bounds__(256,4)) ----
    __threadfence();
    __syncthreads();
    if (threadIdx.x == 0) {
        unsigned n = atomicAdd(&g_bar, 1u);
        if (n == (unsigned)(gridDim.x - 1)) st_release(&g_rel, 1u);
        while (ld_acquire(&g_rel) == 0u) __nanosleep(20);
    }
    __syncthreads();

    // ---- per-thread prefix: P = sum_j A^{chunk-1-j} E_j + A^chunk * seed ----
    float accR = 0.f, accI = 0.f;
    float pwR = 1.f, pwI = 0.f;                     // A^(chunk-1-j)
    for (int j = chunk - 1; j >= 0; j--) {
        float eR = g_er[j * BD + bd];
        float eI = g_ei[j * BD + bd];
        accR = fmaf(pwR, eR, fmaf(-pwI, eI, accR));
        accI = fmaf(pwR, eI, fmaf(pwI, eR, accI));
        float t = pwR * Ar - pwI * Ai;
        pwI = fmaf(pwR, Ai, pwI * Ar);
        pwR = t;
    }
    float seed = lci[d];
    float pr = fmaf(pwR, seed, accR);               // pw = A^chunk here
    float pi = fmaf(pwI, seed, accI);

    // ---- phase 2: pipelined replay, x from L2; out = Re(s)*x, streaming ----
    sr = pr; si = pi;
    float* op = out + (size_t)chunk * LC * BD + bd;
    {
        float xa[UNR], xb[UNR];
#pragma unroll
        for (int k = 0; k < UNR; k++)
            xa[k] = __ldg(xp + (size_t)k * BD);
        for (int n = UNR; n < LC; n += UNR) {
#pragma unroll
            for (int k = 0; k < UNR; k++)
                xb[k] = __ldg(xp + (size_t)(n + k) * BD);
#pragma unroll
            for (int k = 0; k < UNR; k++) {
                float nr = fmaf(cr, sr, fmaf(-ci, si, xa[k]));
                float ni = fmaf(ci, sr, cr * si);
                sr = nr; si = ni;
                __stcs(op + (size_t)(n - UNR + k) * BD, nr * xa[k]);
            }
#pragma unroll
            for (int k = 0; k < UNR; k++) xa[k] = xb[k];
        }
#pragma unroll
        for (int k = 0; k < UNR; k++) {
            float nr = fmaf(cr, sr, fmaf(-ci, si, xa[k]));
            float ni = fmaf(ci, sr, cr * si);
            sr = nr; si = ni;
            __stcs(op + (size_t)(LC - UNR + k) * BD, nr * xa[k]);
        }
    }

    // ---- self-reset barrier state for the next graph replay ----
    if (threadIdx.x == 0) {
        unsigned n2 = atomicAdd(&g_done, 1u);
        if (n2 == (unsigned)(gridDim.x - 1)) {
            g_bar = 0u;
            g_rel = 0u;
            g_done = 0u;
            __threadfence();
        }
    }
}

// ---------------------------------------------------------------------------
extern "C" void kernel_launch(void* const* d_in, const int* in_sizes, int n_in,
                              void* d_out, int out_size) {
    const float* x    = (const float*)d_in[0];  // [L,B,D]
    const float* lmlg = (const float*)d_in[1];  // [D]
    const float* th   = (const float*)d_in[2];  // [D]
    const float* lci  = (const float*)d_in[3];  // [D]
    float* out = (float*)d_out;

    spiral_fused<<<GRID, 256>>>(x, lmlg, th, lci, out);
}